// round 11
// baseline (speedup 1.0000x reference)
#include <cuda_runtime.h>

#define NNODES 50000
#define NB 2
#define FDIM 128
#define EDGES_MAX 800000
#define NODES_PB 32
#define NBLOCKS ((NNODES + NODES_PB - 1) / NODES_PB)   // 1563

// Scratch: __device__ globals only (zero-initialized at module load; the
// scan kernel self-clears g_deg each call so graph replays are identical)
__device__ int g_deg[NNODES];
__device__ int g_rowstart[NNODES + 1];
__device__ int g_cursor[NNODES];
__device__ int g_csr[EDGES_MAX];

// ---------------------------------------------------------------------------
// edges int32 [E,2]; 2 edges per thread
__global__ void k_hist(const int4* __restrict__ edges2, int Epairs) {
    int i = blockIdx.x * blockDim.x + threadIdx.x;
    if (i < Epairs) {
        int4 e2 = edges2[i];
        atomicAdd(&g_deg[e2.y], 1);
        atomicAdd(&g_deg[e2.w], 1);
    }
}

// ---------------------------------------------------------------------------
// Single-block coalesced scan: 1024 threads, int4 passes (50000 = 12500 int4).
// Builds rowstart/cursor, clears g_deg. ~13 passes, all accesses coalesced.
#define SCAN_T 1024
#define SCAN_PASSES ((NNODES / 4 + SCAN_T - 1) / SCAN_T)   // 13

__global__ void __launch_bounds__(SCAN_T)
k_scan() {
    __shared__ int wsum[32];
    __shared__ int running;
    const int tid = threadIdx.x;
    const int lane = tid & 31;
    const int wrp = tid >> 5;
    if (tid == 0) running = 0;

    int4* deg4 = (int4*)g_deg;
    const int n4 = NNODES / 4;   // 12500

    #pragma unroll 1
    for (int p = 0; p < SCAN_PASSES; p++) {
        __syncthreads();                       // running ready / wsum reusable
        const int runLocal = running;
        const int idx = p * SCAN_T + tid;
        int4 v = make_int4(0, 0, 0, 0);
        if (idx < n4) v = deg4[idx];
        const int s = v.x + v.y + v.z + v.w;

        int incl = s;
        #pragma unroll
        for (int off = 1; off < 32; off <<= 1) {
            int t = __shfl_up_sync(0xffffffffu, incl, off);
            if (lane >= off) incl += t;
        }
        if (lane == 31) wsum[wrp] = incl;
        __syncthreads();
        if (wrp == 0) {
            int t = wsum[lane];
            #pragma unroll
            for (int off = 1; off < 32; off <<= 1) {
                int u = __shfl_up_sync(0xffffffffu, t, off);
                if (lane >= off) t += u;
            }
            wsum[lane] = t;                    // inclusive warp sums
        }
        __syncthreads();

        if (idx < n4) {
            const int warpOff = (wrp == 0) ? 0 : wsum[wrp - 1];
            const int ex = runLocal + warpOff + incl - s;
            int4 rs;
            rs.x = ex;
            rs.y = ex + v.x;
            rs.z = rs.y + v.y;
            rs.w = rs.z + v.z;
            ((int4*)g_rowstart)[idx] = rs;     // g_rowstart 16B-aligned (global)
            ((int4*)g_cursor)[idx] = rs;
            deg4[idx] = make_int4(0, 0, 0, 0);
        }
        const int tot = wsum[31];
        __syncthreads();                       // all reads of wsum/running done
        if (tid == 0) running = runLocal + tot;
    }
    __syncthreads();
    if (tid == 0) g_rowstart[NNODES] = running;
}

__global__ void k_fill(const int4* __restrict__ edges2, int Epairs) {
    int i = blockIdx.x * blockDim.x + threadIdx.x;
    if (i < Epairs) {
        int4 e2 = edges2[i];
        int p0 = atomicAdd(&g_cursor[e2.y], 1);
        g_csr[p0] = e2.x;
        int p1 = atomicAdd(&g_cursor[e2.w], 1);
        g_csr[p1] = e2.z;
    }
}

// ---------------------------------------------------------------------------
// Packed f32x2 helpers (FFMA2 path — ptxas won't auto-fuse)
__device__ __forceinline__ unsigned long long pack2(float x, float y) {
    unsigned long long r;
    asm("mov.b64 %0, {%1, %2};" : "=l"(r) : "f"(x), "f"(y));
    return r;
}
__device__ __forceinline__ void unpack2(unsigned long long v, float& x, float& y) {
    asm("mov.b64 {%0, %1}, %2;" : "=f"(x), "=f"(y) : "l"(v));
}
__device__ __forceinline__ void fma2(unsigned long long& d,
                                     unsigned long long a,
                                     unsigned long long b) {
    asm("fma.rn.f32x2 %0, %1, %2, %0;" : "+l"(d) : "l"(a), "l"(b));
}

// ---------------------------------------------------------------------------
// Fused (R7 config + work-stealing gather): 256 threads, 8 warps,
// 32 nodes x both batches per block, 3 blocks/SM.
// Phase 1: warps pull nodes off a shared counter (single-node balancing
//          granularity -> no static straggler tails).
// Phase 2: thread owns 4 cols x 4 nodes, batch-packed FFMA2 accumulators.
__global__ void __launch_bounds__(256, 3)
k_fused(const float* __restrict__ nodes,
        const float* __restrict__ weight,
        const float* __restrict__ bias,
        float* __restrict__ out) {
    __shared__ float2 As2[NODES_PB][FDIM];   // 32KB {batch0, batch1}
    __shared__ float Ws[32][FDIM];           // 16KB (one k-quarter of W)
    __shared__ int ctr;

    const int tid = threadIdx.x;
    const int lane = tid & 31;
    const int node0 = blockIdx.x * NODES_PB;

    if (tid == 0) ctr = 0;
    __syncthreads();

    // ---- phase 1: aggregation (both batches), work-stealing ----
    #pragma unroll 1
    for (;;) {
        int nl = 0;
        if (lane == 0) nl = atomicAdd(&ctr, 1);
        nl = __shfl_sync(0xffffffffu, nl, 0);
        if (nl >= NODES_PB) break;
        const int n = node0 + nl;
        if (n >= NNODES) continue;             // tail block: leave As2 garbage,
                                               // phase 2 discards these rows
        const int rs = g_rowstart[n];
        const int re = g_rowstart[n + 1];
        const float* nb0 = nodes + lane * 4;
        const float* nb1 = nodes + (size_t)NNODES * FDIM + lane * 4;
        float4 acc0 = make_float4(0.f, 0.f, 0.f, 0.f);
        float4 acc1 = make_float4(0.f, 0.f, 0.f, 0.f);
        int i = rs;
        for (; i + 2 <= re; i += 2) {          // MLP = 4
            int s0 = g_csr[i], s1 = g_csr[i + 1];
            float4 a = *(const float4*)(nb0 + (size_t)s0 * FDIM);
            float4 b = *(const float4*)(nb0 + (size_t)s1 * FDIM);
            float4 c = *(const float4*)(nb1 + (size_t)s0 * FDIM);
            float4 d = *(const float4*)(nb1 + (size_t)s1 * FDIM);
            acc0.x += a.x + b.x; acc0.y += a.y + b.y;
            acc0.z += a.z + b.z; acc0.w += a.w + b.w;
            acc1.x += c.x + d.x; acc1.y += c.y + d.y;
            acc1.z += c.z + d.z; acc1.w += c.w + d.w;
        }
        if (i < re) {
            int s0 = g_csr[i];
            float4 a = *(const float4*)(nb0 + (size_t)s0 * FDIM);
            float4 c = *(const float4*)(nb1 + (size_t)s0 * FDIM);
            acc0.x += a.x; acc0.y += a.y; acc0.z += a.z; acc0.w += a.w;
            acc1.x += c.x; acc1.y += c.y; acc1.z += c.z; acc1.w += c.w;
        }
        const float scale = 1.0f / (float)(re - rs + 1);
        float4 lo = make_float4(acc0.x * scale, acc1.x * scale,
                                acc0.y * scale, acc1.y * scale);
        float4 hi = make_float4(acc0.z * scale, acc1.z * scale,
                                acc0.w * scale, acc1.w * scale);
        *(float4*)&As2[nl][lane * 4] = lo;
        *(float4*)&As2[nl][lane * 4 + 2] = hi;
    }

    // ---- phase 2: GEMM ----
    const int colg = tid & 31;    // cols 4*colg .. +4
    const int nodeg = tid >> 5;   // local nodes 4*nodeg .. +4

    const float4 b4 = *(const float4*)(bias + colg * 4);
    unsigned long long acc[4][4];   // [node][col], packed {b0,b1}
    #pragma unroll
    for (int j = 0; j < 4; j++) {
        acc[j][0] = pack2(b4.x, b4.x);
        acc[j][1] = pack2(b4.y, b4.y);
        acc[j][2] = pack2(b4.z, b4.z);
        acc[j][3] = pack2(b4.w, b4.w);
    }

    const float4* w4g = (const float4*)weight;
    #pragma unroll
    for (int kq = 0; kq < 4; kq++) {
        __syncthreads();   // kq=0: As2 ready; kq>0: prior Ws reads done
        #pragma unroll
        for (int i = 0; i < 4; i++)
            ((float4*)Ws)[tid + i * 256] = w4g[kq * 1024 + tid + i * 256];
        __syncthreads();

        #pragma unroll 4
        for (int k = 0; k < 32; k++) {
            const float4 wv = *(const float4*)&Ws[k][colg * 4];
            const unsigned long long w0 = pack2(wv.x, wv.x);
            const unsigned long long w1 = pack2(wv.y, wv.y);
            const unsigned long long w2 = pack2(wv.z, wv.z);
            const unsigned long long w3 = pack2(wv.w, wv.w);
            #pragma unroll
            for (int j = 0; j < 4; j++) {
                const unsigned long long ap =
                    *(const unsigned long long*)&As2[nodeg * 4 + j][kq * 32 + k];
                fma2(acc[j][0], w0, ap);
                fma2(acc[j][1], w1, ap);
                fma2(acc[j][2], w2, ap);
                fma2(acc[j][3], w3, ap);
            }
        }
    }

    // ---- store with relu (unpack batch lanes) ----
    #pragma unroll
    for (int j = 0; j < 4; j++) {
        const int n = node0 + nodeg * 4 + j;
        if (n < NNODES) {
            float x0, y0, x1, y1, x2, y2, x3, y3;
            unpack2(acc[j][0], x0, y0);
            unpack2(acc[j][1], x1, y1);
            unpack2(acc[j][2], x2, y2);
            unpack2(acc[j][3], x3, y3);
            float4 o0 = make_float4(fmaxf(x0, 0.f), fmaxf(x1, 0.f),
                                    fmaxf(x2, 0.f), fmaxf(x3, 0.f));
            float4 o1 = make_float4(fmaxf(y0, 0.f), fmaxf(y1, 0.f),
                                    fmaxf(y2, 0.f), fmaxf(y3, 0.f));
            *(float4*)(out + (size_t)n * FDIM + colg * 4) = o0;
            *(float4*)(out + (size_t)(NNODES + n) * FDIM + colg * 4) = o1;
        }
    }
}

// ---------------------------------------------------------------------------
extern "C" void kernel_launch(void* const* d_in, const int* in_sizes, int n_in,
                              void* d_out, int out_size) {
    const float* nodes = (const float*)d_in[0];
    const int4* edges2 = (const int4*)d_in[1];   // int32 [E,2]
    const float* weight = (const float*)d_in[2];
    const float* bias = (const float*)d_in[3];
    float* out = (float*)d_out;

    int E = in_sizes[1] / 2;
    if (E > EDGES_MAX) E = EDGES_MAX;
    int Epairs = E / 2;

    k_hist<<<(Epairs + 255) / 256, 256>>>(edges2, Epairs);
    k_scan<<<1, SCAN_T>>>();
    k_fill<<<(Epairs + 255) / 256, 256>>>(edges2, Epairs);
    k_fused<<<NBLOCKS, 256>>>(nodes, weight, bias, out);
}

// round 12
// speedup vs baseline: 1.0009x; 1.0009x over previous
#include <cuda_runtime.h>

#define NNODES 50000
#define NB 2
#define FDIM 128
#define EDGES_MAX 800000
#define NODES_PB 64
#define NBLOCKS ((NNODES + NODES_PB - 1) / NODES_PB)   // 782
#define SCAN_BLOCKS ((NNODES + 255) / 256)             // 196

// Scratch: __device__ globals only (zero-initialized at module load; the
// scan pipeline self-clears g_deg each call so graph replays are identical)
__device__ int g_deg[NNODES];
__device__ int g_rowstart[NNODES + 1];
__device__ int g_cursor[NNODES];
__device__ int g_exloc[NNODES];
__device__ int g_bsum[SCAN_BLOCKS];
__device__ int g_csr[EDGES_MAX];

// ---------------------------------------------------------------------------
// edges int32 [E,2]; 2 edges per thread
__global__ void k_hist(const int4* __restrict__ edges2, int Epairs) {
    int i = blockIdx.x * blockDim.x + threadIdx.x;
    if (i < Epairs) {
        int4 e2 = edges2[i];
        atomicAdd(&g_deg[e2.y], 1);
        atomicAdd(&g_deg[e2.w], 1);
    }
}

// A: per-block exclusive scan of g_deg (coalesced), block sums to g_bsum
__global__ void __launch_bounds__(256)
k_scan_local() {
    __shared__ int wsum[8];
    const int tid = threadIdx.x;
    const int i = blockIdx.x * 256 + tid;
    const int lane = tid & 31;
    const int wrp = tid >> 5;

    int val = (i < NNODES) ? g_deg[i] : 0;
    int incl = val;
    #pragma unroll
    for (int off = 1; off < 32; off <<= 1) {
        int v = __shfl_up_sync(0xffffffffu, incl, off);
        if (lane >= off) incl += v;
    }
    if (lane == 31) wsum[wrp] = incl;
    __syncthreads();
    if (wrp == 0) {
        int s = (lane < 8) ? wsum[lane] : 0;
        #pragma unroll
        for (int off = 1; off < 8; off <<= 1) {
            int v = __shfl_up_sync(0xffffffffu, s, off);
            if (lane >= off) s += v;
        }
        if (lane < 8) wsum[lane] = s;
    }
    __syncthreads();
    const int warpOff = (wrp == 0) ? 0 : wsum[wrp - 1];
    if (i < NNODES) g_exloc[i] = warpOff + incl - val;
    if (tid == 255) g_bsum[blockIdx.x] = warpOff + incl;
}

// B (merged): each block computes its bsum-prefix with warp 0, then
// distributes rowstart/cursor and self-clears g_deg. Last block writes total.
__global__ void __launch_bounds__(256)
k_scan_add() {
    __shared__ int blockOff;
    const int tid = threadIdx.x;
    const int bid = blockIdx.x;

    if (tid < 32) {
        int s = 0;
        for (int i = tid; i < bid; i += 32) s += g_bsum[i];
        int own = (bid == SCAN_BLOCKS - 1 && tid == 0)
                      ? g_bsum[SCAN_BLOCKS - 1] : 0;   // for grand total
        #pragma unroll
        for (int off = 16; off > 0; off >>= 1)
            s += __shfl_down_sync(0xffffffffu, s, off);
        if (tid == 0) {
            blockOff = s;
            if (bid == SCAN_BLOCKS - 1) g_rowstart[NNODES] = s + own;
        }
    }
    __syncthreads();

    const int i = bid * 256 + tid;
    if (i < NNODES) {
        const int rs = g_exloc[i] + blockOff;
        g_rowstart[i] = rs;
        g_cursor[i] = rs;
        g_deg[i] = 0;
    }
}

__global__ void k_fill(const int4* __restrict__ edges2, int Epairs) {
    int i = blockIdx.x * blockDim.x + threadIdx.x;
    if (i < Epairs) {
        int4 e2 = edges2[i];
        int p0 = atomicAdd(&g_cursor[e2.y], 1);
        g_csr[p0] = e2.x;
        int p1 = atomicAdd(&g_cursor[e2.w], 1);
        g_csr[p1] = e2.z;
    }
}

// ---------------------------------------------------------------------------
// Packed f32x2 helpers (FFMA2 path — ptxas won't auto-fuse)
__device__ __forceinline__ unsigned long long pack2(float x, float y) {
    unsigned long long r;
    asm("mov.b64 %0, {%1, %2};" : "=l"(r) : "f"(x), "f"(y));
    return r;
}
__device__ __forceinline__ void unpack2(unsigned long long v, float& x, float& y) {
    asm("mov.b64 {%0, %1}, %2;" : "=f"(x), "=f"(y) : "l"(v));
}
__device__ __forceinline__ void fma2(unsigned long long& d,
                                     unsigned long long a,
                                     unsigned long long b) {
    asm("fma.rn.f32x2 %0, %1, %2, %0;" : "+l"(d) : "l"(a), "l"(b));
}

// ---------------------------------------------------------------------------
// Fused, 64-node tile: 512 threads (16 warps), 64 nodes x both batches,
// 80KB dynamic smem, 2 blocks/SM (32 warps/SM).
// W smem phases amortize over 2x more nodes than the 32-node tile: GEMM
// L1 phases drop from 8/k/warp-equivalent 256/node to 192/node.
// Per-thread shape identical to the proven R7 config (4 nodes x 4 cols).
#define SMEM_BYTES (NODES_PB * FDIM * 8 + 32 * FDIM * 4)   // 80KB

__global__ void __launch_bounds__(512, 2)
k_fused(const float* __restrict__ nodes,
        const float* __restrict__ weight,
        const float* __restrict__ bias,
        float* __restrict__ out) {
    extern __shared__ char smem_raw[];
    float2 (*As2)[FDIM] = (float2 (*)[FDIM])smem_raw;            // 64KB
    float (*Ws)[FDIM] = (float (*)[FDIM])(smem_raw + NODES_PB * FDIM * 8);

    const int tid = threadIdx.x;
    const int w = tid >> 5;          // warp 0..15
    const int lane = tid & 31;
    const int node0 = blockIdx.x * NODES_PB;

    // ---- phase 1: aggregation (both batches), MLP 4, 4 nodes/warp ----
    #pragma unroll 1
    for (int j = 0; j < 4; j++) {
        const int nl = w * 4 + j;            // local node 0..63
        const int n = node0 + nl;
        float4 acc0 = make_float4(0.f, 0.f, 0.f, 0.f);
        float4 acc1 = make_float4(0.f, 0.f, 0.f, 0.f);
        float scale = 0.0f;
        if (n < NNODES) {
            const int rs = g_rowstart[n];
            const int re = g_rowstart[n + 1];
            const float* nb0 = nodes + lane * 4;
            const float* nb1 = nodes + (size_t)NNODES * FDIM + lane * 4;
            int i = rs;
            for (; i + 2 <= re; i += 2) {
                int s0 = g_csr[i], s1 = g_csr[i + 1];
                float4 a = *(const float4*)(nb0 + (size_t)s0 * FDIM);
                float4 b = *(const float4*)(nb0 + (size_t)s1 * FDIM);
                float4 c = *(const float4*)(nb1 + (size_t)s0 * FDIM);
                float4 d = *(const float4*)(nb1 + (size_t)s1 * FDIM);
                acc0.x += a.x + b.x; acc0.y += a.y + b.y;
                acc0.z += a.z + b.z; acc0.w += a.w + b.w;
                acc1.x += c.x + d.x; acc1.y += c.y + d.y;
                acc1.z += c.z + d.z; acc1.w += c.w + d.w;
            }
            if (i < re) {
                int s0 = g_csr[i];
                float4 a = *(const float4*)(nb0 + (size_t)s0 * FDIM);
                float4 c = *(const float4*)(nb1 + (size_t)s0 * FDIM);
                acc0.x += a.x; acc0.y += a.y; acc0.z += a.z; acc0.w += a.w;
                acc1.x += c.x; acc1.y += c.y; acc1.z += c.z; acc1.w += c.w;
            }
            scale = 1.0f / (float)(re - rs + 1);
        }
        float4 lo = make_float4(acc0.x * scale, acc1.x * scale,
                                acc0.y * scale, acc1.y * scale);
        float4 hi = make_float4(acc0.z * scale, acc1.z * scale,
                                acc0.w * scale, acc1.w * scale);
        *(float4*)&As2[nl][lane * 4] = lo;
        *(float4*)&As2[nl][lane * 4 + 2] = hi;
    }

    // ---- phase 2: GEMM ----
    const int colg = tid & 31;    // cols 4*colg .. +4
    const int nodeg = tid >> 5;   // local nodes 4*nodeg .. +4 (16 groups x 4 = 64)

    const float4 b4 = *(const float4*)(bias + colg * 4);
    unsigned long long acc[4][4];   // [node][col], packed {b0,b1}
    #pragma unroll
    for (int j = 0; j < 4; j++) {
        acc[j][0] = pack2(b4.x, b4.x);
        acc[j][1] = pack2(b4.y, b4.y);
        acc[j][2] = pack2(b4.z, b4.z);
        acc[j][3] = pack2(b4.w, b4.w);
    }

    const float4* w4g = (const float4*)weight;
    #pragma unroll
    for (int kq = 0; kq < 4; kq++) {
        __syncthreads();   // kq=0: As2 ready; kq>0: prior Ws reads done
        #pragma unroll
        for (int i = 0; i < 2; i++)
            ((float4*)Ws)[tid + i * 512] = w4g[kq * 1024 + tid + i * 512];
        __syncthreads();

        #pragma unroll 4
        for (int k = 0; k < 32; k++) {
            const float4 wv = *(const float4*)&Ws[k][colg * 4];
            const unsigned long long w0 = pack2(wv.x, wv.x);
            const unsigned long long w1 = pack2(wv.y, wv.y);
            const unsigned long long w2 = pack2(wv.z, wv.z);
            const unsigned long long w3 = pack2(wv.w, wv.w);
            #pragma unroll
            for (int j = 0; j < 4; j++) {
                const unsigned long long ap =
                    *(const unsigned long long*)&As2[nodeg * 4 + j][kq * 32 + k];
                fma2(acc[j][0], w0, ap);
                fma2(acc[j][1], w1, ap);
                fma2(acc[j][2], w2, ap);
                fma2(acc[j][3], w3, ap);
            }
        }
    }

    // ---- store with relu (unpack batch lanes) ----
    #pragma unroll
    for (int j = 0; j < 4; j++) {
        const int n = node0 + nodeg * 4 + j;
        if (n < NNODES) {
            float x0, y0, x1, y1, x2, y2, x3, y3;
            unpack2(acc[j][0], x0, y0);
            unpack2(acc[j][1], x1, y1);
            unpack2(acc[j][2], x2, y2);
            unpack2(acc[j][3], x3, y3);
            float4 o0 = make_float4(fmaxf(x0, 0.f), fmaxf(x1, 0.f),
                                    fmaxf(x2, 0.f), fmaxf(x3, 0.f));
            float4 o1 = make_float4(fmaxf(y0, 0.f), fmaxf(y1, 0.f),
                                    fmaxf(y2, 0.f), fmaxf(y3, 0.f));
            *(float4*)(out + (size_t)n * FDIM + colg * 4) = o0;
            *(float4*)(out + (size_t)(NNODES + n) * FDIM + colg * 4) = o1;
        }
    }
}

// ---------------------------------------------------------------------------
extern "C" void kernel_launch(void* const* d_in, const int* in_sizes, int n_in,
                              void* d_out, int out_size) {
    const float* nodes = (const float*)d_in[0];
    const int4* edges2 = (const int4*)d_in[1];   // int32 [E,2]
    const float* weight = (const float*)d_in[2];
    const float* bias = (const float*)d_in[3];
    float* out = (float*)d_out;

    int E = in_sizes[1] / 2;
    if (E > EDGES_MAX) E = EDGES_MAX;
    int Epairs = E / 2;

    // Opt-in >48KB dynamic smem (host-side attribute; idempotent, not a
    // stream op — safe at capture time). No allocations anywhere.
    cudaFuncSetAttribute(k_fused, cudaFuncAttributeMaxDynamicSharedMemorySize,
                         SMEM_BYTES);

    k_hist<<<(Epairs + 255) / 256, 256>>>(edges2, Epairs);
    k_scan_local<<<SCAN_BLOCKS, 256>>>();
    k_scan_add<<<SCAN_BLOCKS, 256>>>();
    k_fill<<<(Epairs + 255) / 256, 256>>>(edges2, Epairs);
    k_fused<<<NBLOCKS, 512, SMEM_BYTES>>>(nodes, weight, bias, out);
}

// round 13
// speedup vs baseline: 1.0885x; 1.0876x over previous
#include <cuda_runtime.h>

#define NNODES 50000
#define NB 2
#define FDIM 128
#define EDGES_MAX 800000
#define NODES_PB 32
#define NBLOCKS ((NNODES + NODES_PB - 1) / NODES_PB)   // 1563
#define SCAN_BLOCKS ((NNODES + 255) / 256)             // 196

// Scratch: __device__ globals only (zero-initialized at module load; the
// scan pipeline self-clears g_deg each call so graph replays are identical)
__device__ int g_deg[NNODES];
__device__ int g_rowstart[NNODES + 1];
__device__ int g_exloc[NNODES];
__device__ int g_bsum[SCAN_BLOCKS];
__device__ int g_ticket[EDGES_MAX];    // arrival index within dst bucket
__device__ int g_csr[EDGES_MAX];

// ---------------------------------------------------------------------------
// edges int32 [E,2]; 2 edges per thread. Records per-edge arrival tickets.
__global__ void k_hist(const int4* __restrict__ edges2, int Epairs) {
    int i = blockIdx.x * blockDim.x + threadIdx.x;
    if (i < Epairs) {
        int4 e2 = edges2[i];
        int t0 = atomicAdd(&g_deg[e2.y], 1);
        int t1 = atomicAdd(&g_deg[e2.w], 1);
        *(int2*)&g_ticket[2 * i] = make_int2(t0, t1);   // coalesced
    }
}

// A: per-block exclusive scan of g_deg (coalesced), block sums to g_bsum
__global__ void __launch_bounds__(256)
k_scan_local() {
    __shared__ int wsum[8];
    const int tid = threadIdx.x;
    const int i = blockIdx.x * 256 + tid;
    const int lane = tid & 31;
    const int wrp = tid >> 5;

    int val = (i < NNODES) ? g_deg[i] : 0;
    int incl = val;
    #pragma unroll
    for (int off = 1; off < 32; off <<= 1) {
        int v = __shfl_up_sync(0xffffffffu, incl, off);
        if (lane >= off) incl += v;
    }
    if (lane == 31) wsum[wrp] = incl;
    __syncthreads();
    if (wrp == 0) {
        int s = (lane < 8) ? wsum[lane] : 0;
        #pragma unroll
        for (int off = 1; off < 8; off <<= 1) {
            int v = __shfl_up_sync(0xffffffffu, s, off);
            if (lane >= off) s += v;
        }
        if (lane < 8) wsum[lane] = s;
    }
    __syncthreads();
    const int warpOff = (wrp == 0) ? 0 : wsum[wrp - 1];
    if (i < NNODES) g_exloc[i] = warpOff + incl - val;
    if (tid == 255) g_bsum[blockIdx.x] = warpOff + incl;
}

// B (merged): block computes its bsum-prefix with warp 0, then distributes
// rowstart and self-clears g_deg. Last block writes the grand total.
__global__ void __launch_bounds__(256)
k_scan_add() {
    __shared__ int blockOff;
    const int tid = threadIdx.x;
    const int bid = blockIdx.x;

    if (tid < 32) {
        int s = 0;
        for (int i = tid; i < bid; i += 32) s += g_bsum[i];
        int own = (bid == SCAN_BLOCKS - 1 && tid == 0)
                      ? g_bsum[SCAN_BLOCKS - 1] : 0;
        #pragma unroll
        for (int off = 16; off > 0; off >>= 1)
            s += __shfl_down_sync(0xffffffffu, s, off);
        if (tid == 0) {
            blockOff = s;
            if (bid == SCAN_BLOCKS - 1) g_rowstart[NNODES] = s + own;
        }
    }
    __syncthreads();

    const int i = bid * 256 + tid;
    if (i < NNODES) {
        g_rowstart[i] = g_exloc[i] + blockOff;
        g_deg[i] = 0;
    }
}

// Atomic-free CSR fill: slot = rowstart[dst] + ticket (precomputed in hist)
__global__ void k_fill(const int4* __restrict__ edges2, int Epairs) {
    int i = blockIdx.x * blockDim.x + threadIdx.x;
    if (i < Epairs) {
        int4 e2 = edges2[i];
        int2 t = *(const int2*)&g_ticket[2 * i];
        g_csr[g_rowstart[e2.y] + t.x] = e2.x;
        g_csr[g_rowstart[e2.w] + t.y] = e2.z;
    }
}

// ---------------------------------------------------------------------------
// Packed f32x2 helpers (FFMA2 path — ptxas won't auto-fuse)
__device__ __forceinline__ unsigned long long pack2(float x, float y) {
    unsigned long long r;
    asm("mov.b64 %0, {%1, %2};" : "=l"(r) : "f"(x), "f"(y));
    return r;
}
__device__ __forceinline__ void unpack2(unsigned long long v, float& x, float& y) {
    asm("mov.b64 {%0, %1}, %2;" : "=f"(x), "=f"(y) : "l"(v));
}
__device__ __forceinline__ void fma2(unsigned long long& d,
                                     unsigned long long a,
                                     unsigned long long b) {
    asm("fma.rn.f32x2 %0, %1, %2, %0;" : "+l"(d) : "l"(a), "l"(b));
}

// ---------------------------------------------------------------------------
// Fused (R7 configuration — frozen, proven best): 256 threads, 8 warps,
// 32 nodes x both batches per block, 3 blocks/SM. GEMM is exactly co-bound
// (FFMA2 issue == L1 phases per SMSP) — do not perturb.
__global__ void __launch_bounds__(256, 3)
k_fused(const float* __restrict__ nodes,
        const float* __restrict__ weight,
        const float* __restrict__ bias,
        float* __restrict__ out) {
    __shared__ float2 As2[NODES_PB][FDIM];   // 32KB {batch0, batch1}
    __shared__ float Ws[32][FDIM];           // 16KB (one k-quarter of W)

    const int tid = threadIdx.x;
    const int w = tid >> 5;
    const int lane = tid & 31;
    const int node0 = blockIdx.x * NODES_PB;

    // ---- phase 1: aggregation (both batches), MLP 4 ----
    #pragma unroll 1
    for (int j = 0; j < 4; j++) {
        const int nl = w * 4 + j;            // local node 0..31
        const int n = node0 + nl;
        float4 acc0 = make_float4(0.f, 0.f, 0.f, 0.f);
        float4 acc1 = make_float4(0.f, 0.f, 0.f, 0.f);
        float scale = 0.0f;
        if (n < NNODES) {
            const int rs = g_rowstart[n];
            const int re = g_rowstart[n + 1];
            const float* nb0 = nodes + lane * 4;
            const float* nb1 = nodes + (size_t)NNODES * FDIM + lane * 4;
            int i = rs;
            for (; i + 2 <= re; i += 2) {
                int s0 = g_csr[i], s1 = g_csr[i + 1];
                float4 a = *(const float4*)(nb0 + (size_t)s0 * FDIM);
                float4 b = *(const float4*)(nb0 + (size_t)s1 * FDIM);
                float4 c = *(const float4*)(nb1 + (size_t)s0 * FDIM);
                float4 d = *(const float4*)(nb1 + (size_t)s1 * FDIM);
                acc0.x += a.x + b.x; acc0.y += a.y + b.y;
                acc0.z += a.z + b.z; acc0.w += a.w + b.w;
                acc1.x += c.x + d.x; acc1.y += c.y + d.y;
                acc1.z += c.z + d.z; acc1.w += c.w + d.w;
            }
            if (i < re) {
                int s0 = g_csr[i];
                float4 a = *(const float4*)(nb0 + (size_t)s0 * FDIM);
                float4 c = *(const float4*)(nb1 + (size_t)s0 * FDIM);
                acc0.x += a.x; acc0.y += a.y; acc0.z += a.z; acc0.w += a.w;
                acc1.x += c.x; acc1.y += c.y; acc1.z += c.z; acc1.w += c.w;
            }
            scale = 1.0f / (float)(re - rs + 1);
        }
        float4 lo = make_float4(acc0.x * scale, acc1.x * scale,
                                acc0.y * scale, acc1.y * scale);
        float4 hi = make_float4(acc0.z * scale, acc1.z * scale,
                                acc0.w * scale, acc1.w * scale);
        *(float4*)&As2[nl][lane * 4] = lo;
        *(float4*)&As2[nl][lane * 4 + 2] = hi;
    }

    // ---- phase 2: GEMM ----
    const int colg = tid & 31;    // cols 4*colg .. +4
    const int nodeg = tid >> 5;   // local nodes 4*nodeg .. +4

    const float4 b4 = *(const float4*)(bias + colg * 4);
    unsigned long long acc[4][4];   // [node][col], packed {b0,b1}
    #pragma unroll
    for (int j = 0; j < 4; j++) {
        acc[j][0] = pack2(b4.x, b4.x);
        acc[j][1] = pack2(b4.y, b4.y);
        acc[j][2] = pack2(b4.z, b4.z);
        acc[j][3] = pack2(b4.w, b4.w);
    }

    const float4* w4g = (const float4*)weight;
    #pragma unroll
    for (int kq = 0; kq < 4; kq++) {
        __syncthreads();   // kq=0: As2 ready; kq>0: prior Ws reads done
        #pragma unroll
        for (int i = 0; i < 4; i++)
            ((float4*)Ws)[tid + i * 256] = w4g[kq * 1024 + tid + i * 256];
        __syncthreads();

        #pragma unroll 4
        for (int k = 0; k < 32; k++) {
            const float4 wv = *(const float4*)&Ws[k][colg * 4];
            const unsigned long long w0 = pack2(wv.x, wv.x);
            const unsigned long long w1 = pack2(wv.y, wv.y);
            const unsigned long long w2 = pack2(wv.z, wv.z);
            const unsigned long long w3 = pack2(wv.w, wv.w);
            #pragma unroll
            for (int j = 0; j < 4; j++) {
                const unsigned long long ap =
                    *(const unsigned long long*)&As2[nodeg * 4 + j][kq * 32 + k];
                fma2(acc[j][0], w0, ap);
                fma2(acc[j][1], w1, ap);
                fma2(acc[j][2], w2, ap);
                fma2(acc[j][3], w3, ap);
            }
        }
    }

    // ---- store with relu (unpack batch lanes) ----
    #pragma unroll
    for (int j = 0; j < 4; j++) {
        const int n = node0 + nodeg * 4 + j;
        if (n < NNODES) {
            float x0, y0, x1, y1, x2, y2, x3, y3;
            unpack2(acc[j][0], x0, y0);
            unpack2(acc[j][1], x1, y1);
            unpack2(acc[j][2], x2, y2);
            unpack2(acc[j][3], x3, y3);
            float4 o0 = make_float4(fmaxf(x0, 0.f), fmaxf(x1, 0.f),
                                    fmaxf(x2, 0.f), fmaxf(x3, 0.f));
            float4 o1 = make_float4(fmaxf(y0, 0.f), fmaxf(y1, 0.f),
                                    fmaxf(y2, 0.f), fmaxf(y3, 0.f));
            *(float4*)(out + (size_t)n * FDIM + colg * 4) = o0;
            *(float4*)(out + (size_t)(NNODES + n) * FDIM + colg * 4) = o1;
        }
    }
}

// ---------------------------------------------------------------------------
extern "C" void kernel_launch(void* const* d_in, const int* in_sizes, int n_in,
                              void* d_out, int out_size) {
    const float* nodes = (const float*)d_in[0];
    const int4* edges2 = (const int4*)d_in[1];   // int32 [E,2]
    const float* weight = (const float*)d_in[2];
    const float* bias = (const float*)d_in[3];
    float* out = (float*)d_out;

    int E = in_sizes[1] / 2;
    if (E > EDGES_MAX) E = EDGES_MAX;
    int Epairs = E / 2;

    k_hist<<<(Epairs + 255) / 256, 256>>>(edges2, Epairs);
    k_scan_local<<<SCAN_BLOCKS, 256>>>();
    k_scan_add<<<SCAN_BLOCKS, 256>>>();
    k_fill<<<(Epairs + 255) / 256, 256>>>(edges2, Epairs);
    k_fused<<<NBLOCKS, 256>>>(nodes, weight, bias, out);
}

// round 14
// speedup vs baseline: 1.0908x; 1.0021x over previous
#include <cuda_runtime.h>

#define NNODES 50000
#define NB 2
#define FDIM 128
#define EDGES_MAX 800000
#define NODES_PB 32
#define NBLOCKS ((NNODES + NODES_PB - 1) / NODES_PB)   // 1563
#define SCAN_BLOCKS ((NNODES + 255) / 256)             // 196

// Scratch: __device__ globals only (zero-initialized at module load; the
// scan pipeline self-clears g_deg each call so graph replays are identical)
__device__ int g_deg[NNODES];
__device__ int g_rowstart[NNODES + 1];
__device__ int g_exloc[NNODES];
__device__ int g_bsum[SCAN_BLOCKS];
__device__ int g_ticket[EDGES_MAX];    // arrival index within dst bucket
__device__ int g_csr[EDGES_MAX];

// ---------------------------------------------------------------------------
// edges int32 [E,2]; 2 edges per thread. Records per-edge arrival tickets.
__global__ void k_hist(const int4* __restrict__ edges2, int Epairs) {
    int i = blockIdx.x * blockDim.x + threadIdx.x;
    if (i < Epairs) {
        int4 e2 = edges2[i];
        int t0 = atomicAdd(&g_deg[e2.y], 1);
        int t1 = atomicAdd(&g_deg[e2.w], 1);
        *(int2*)&g_ticket[2 * i] = make_int2(t0, t1);   // coalesced
    }
}

// A: per-block exclusive scan of g_deg (coalesced), block sums to g_bsum
__global__ void __launch_bounds__(256)
k_scan_local() {
    __shared__ int wsum[8];
    const int tid = threadIdx.x;
    const int i = blockIdx.x * 256 + tid;
    const int lane = tid & 31;
    const int wrp = tid >> 5;

    int val = (i < NNODES) ? g_deg[i] : 0;
    int incl = val;
    #pragma unroll
    for (int off = 1; off < 32; off <<= 1) {
        int v = __shfl_up_sync(0xffffffffu, incl, off);
        if (lane >= off) incl += v;
    }
    if (lane == 31) wsum[wrp] = incl;
    __syncthreads();
    if (wrp == 0) {
        int s = (lane < 8) ? wsum[lane] : 0;
        #pragma unroll
        for (int off = 1; off < 8; off <<= 1) {
            int v = __shfl_up_sync(0xffffffffu, s, off);
            if (lane >= off) s += v;
        }
        if (lane < 8) wsum[lane] = s;
    }
    __syncthreads();
    const int warpOff = (wrp == 0) ? 0 : wsum[wrp - 1];
    if (i < NNODES) g_exloc[i] = warpOff + incl - val;
    if (tid == 255) g_bsum[blockIdx.x] = warpOff + incl;
}

// B (merged): block computes its bsum-prefix with warp 0, then distributes
// rowstart and self-clears g_deg. Last block writes the grand total.
__global__ void __launch_bounds__(256)
k_scan_add() {
    __shared__ int blockOff;
    const int tid = threadIdx.x;
    const int bid = blockIdx.x;

    if (tid < 32) {
        int s = 0;
        for (int i = tid; i < bid; i += 32) s += g_bsum[i];
        int own = (bid == SCAN_BLOCKS - 1 && tid == 0)
                      ? g_bsum[SCAN_BLOCKS - 1] : 0;
        #pragma unroll
        for (int off = 16; off > 0; off >>= 1)
            s += __shfl_down_sync(0xffffffffu, s, off);
        if (tid == 0) {
            blockOff = s;
            if (bid == SCAN_BLOCKS - 1) g_rowstart[NNODES] = s + own;
        }
    }
    __syncthreads();

    const int i = bid * 256 + tid;
    if (i < NNODES) {
        g_rowstart[i] = g_exloc[i] + blockOff;
        g_deg[i] = 0;
    }
}

// Atomic-free CSR fill: slot = rowstart[dst] + ticket (precomputed in hist)
__global__ void k_fill(const int4* __restrict__ edges2, int Epairs) {
    int i = blockIdx.x * blockDim.x + threadIdx.x;
    if (i < Epairs) {
        int4 e2 = edges2[i];
        int2 t = *(const int2*)&g_ticket[2 * i];
        g_csr[g_rowstart[e2.y] + t.x] = e2.x;
        g_csr[g_rowstart[e2.w] + t.y] = e2.z;
    }
}

// ---------------------------------------------------------------------------
// Packed f32x2 helpers (FFMA2 path — ptxas won't auto-fuse)
__device__ __forceinline__ unsigned long long pack2(float x, float y) {
    unsigned long long r;
    asm("mov.b64 %0, {%1, %2};" : "=l"(r) : "f"(x), "f"(y));
    return r;
}
__device__ __forceinline__ void unpack2(unsigned long long v, float& x, float& y) {
    asm("mov.b64 {%0, %1}, %2;" : "=f"(x), "=f"(y) : "l"(v));
}
__device__ __forceinline__ void fma2(unsigned long long& d,
                                     unsigned long long a,
                                     unsigned long long b) {
    asm("fma.rn.f32x2 %0, %1, %2, %0;" : "+l"(d) : "l"(a), "l"(b));
}

// ---------------------------------------------------------------------------
// Fused (R7 base; GEMM A operand fetched as k-pair LDS.128 broadcast):
// 256 threads, 8 warps, 32 nodes x both batches per block, 3 blocks/SM.
// Per 2k per warp: W 8 phases + A 4 phases = 6 phases/k (was 8/k).
__global__ void __launch_bounds__(256, 3)
k_fused(const float* __restrict__ nodes,
        const float* __restrict__ weight,
        const float* __restrict__ bias,
        float* __restrict__ out) {
    __shared__ float2 As2[NODES_PB][FDIM];   // 32KB {batch0, batch1}
    __shared__ float Ws[32][FDIM];           // 16KB (one k-quarter of W)

    const int tid = threadIdx.x;
    const int w = tid >> 5;
    const int lane = tid & 31;
    const int node0 = blockIdx.x * NODES_PB;

    // ---- phase 1: aggregation (both batches), MLP 4 ----
    #pragma unroll 1
    for (int j = 0; j < 4; j++) {
        const int nl = w * 4 + j;            // local node 0..31
        const int n = node0 + nl;
        float4 acc0 = make_float4(0.f, 0.f, 0.f, 0.f);
        float4 acc1 = make_float4(0.f, 0.f, 0.f, 0.f);
        float scale = 0.0f;
        if (n < NNODES) {
            const int rs = g_rowstart[n];
            const int re = g_rowstart[n + 1];
            const float* nb0 = nodes + lane * 4;
            const float* nb1 = nodes + (size_t)NNODES * FDIM + lane * 4;
            int i = rs;
            for (; i + 2 <= re; i += 2) {
                int s0 = g_csr[i], s1 = g_csr[i + 1];
                float4 a = *(const float4*)(nb0 + (size_t)s0 * FDIM);
                float4 b = *(const float4*)(nb0 + (size_t)s1 * FDIM);
                float4 c = *(const float4*)(nb1 + (size_t)s0 * FDIM);
                float4 d = *(const float4*)(nb1 + (size_t)s1 * FDIM);
                acc0.x += a.x + b.x; acc0.y += a.y + b.y;
                acc0.z += a.z + b.z; acc0.w += a.w + b.w;
                acc1.x += c.x + d.x; acc1.y += c.y + d.y;
                acc1.z += c.z + d.z; acc1.w += c.w + d.w;
            }
            if (i < re) {
                int s0 = g_csr[i];
                float4 a = *(const float4*)(nb0 + (size_t)s0 * FDIM);
                float4 c = *(const float4*)(nb1 + (size_t)s0 * FDIM);
                acc0.x += a.x; acc0.y += a.y; acc0.z += a.z; acc0.w += a.w;
                acc1.x += c.x; acc1.y += c.y; acc1.z += c.z; acc1.w += c.w;
            }
            scale = 1.0f / (float)(re - rs + 1);
        }
        float4 lo = make_float4(acc0.x * scale, acc1.x * scale,
                                acc0.y * scale, acc1.y * scale);
        float4 hi = make_float4(acc0.z * scale, acc1.z * scale,
                                acc0.w * scale, acc1.w * scale);
        *(float4*)&As2[nl][lane * 4] = lo;
        *(float4*)&As2[nl][lane * 4 + 2] = hi;
    }

    // ---- phase 2: GEMM ----
    const int colg = tid & 31;    // cols 4*colg .. +4
    const int nodeg = tid >> 5;   // local nodes 4*nodeg .. +4

    const float4 b4 = *(const float4*)(bias + colg * 4);
    unsigned long long acc[4][4];   // [node][col], packed {b0,b1}
    #pragma unroll
    for (int j = 0; j < 4; j++) {
        acc[j][0] = pack2(b4.x, b4.x);
        acc[j][1] = pack2(b4.y, b4.y);
        acc[j][2] = pack2(b4.z, b4.z);
        acc[j][3] = pack2(b4.w, b4.w);
    }

    const float4* w4g = (const float4*)weight;
    #pragma unroll
    for (int kq = 0; kq < 4; kq++) {
        __syncthreads();   // kq=0: As2 ready; kq>0: prior Ws reads done
        #pragma unroll
        for (int i = 0; i < 4; i++)
            ((float4*)Ws)[tid + i * 256] = w4g[kq * 1024 + tid + i * 256];
        __syncthreads();

        #pragma unroll 2
        for (int k2 = 0; k2 < 16; k2++) {
            // W packs for both k's of the pair (16 regs, reused by 4 nodes)
            const float4 wva = *(const float4*)&Ws[k2 * 2][colg * 4];
            const float4 wvb = *(const float4*)&Ws[k2 * 2 + 1][colg * 4];
            const unsigned long long wa0 = pack2(wva.x, wva.x);
            const unsigned long long wa1 = pack2(wva.y, wva.y);
            const unsigned long long wa2 = pack2(wva.z, wva.z);
            const unsigned long long wa3 = pack2(wva.w, wva.w);
            const unsigned long long wb0 = pack2(wvb.x, wvb.x);
            const unsigned long long wb1 = pack2(wvb.y, wvb.y);
            const unsigned long long wb2 = pack2(wvb.z, wvb.z);
            const unsigned long long wb3 = pack2(wvb.w, wvb.w);
            #pragma unroll
            for (int j = 0; j < 4; j++) {
                // one broadcast LDS.128: packed A for k2*2 and k2*2+1
                const ulonglong2 ap =
                    *(const ulonglong2*)&As2[nodeg * 4 + j][kq * 32 + k2 * 2];
                fma2(acc[j][0], wa0, ap.x);
                fma2(acc[j][1], wa1, ap.x);
                fma2(acc[j][2], wa2, ap.x);
                fma2(acc[j][3], wa3, ap.x);
                fma2(acc[j][0], wb0, ap.y);
                fma2(acc[j][1], wb1, ap.y);
                fma2(acc[j][2], wb2, ap.y);
                fma2(acc[j][3], wb3, ap.y);
            }
        }
    }

    // ---- store with relu (unpack batch lanes) ----
    #pragma unroll
    for (int j = 0; j < 4; j++) {
        const int n = node0 + nodeg * 4 + j;
        if (n < NNODES) {
            float x0, y0, x1, y1, x2, y2, x3, y3;
            unpack2(acc[j][0], x0, y0);
            unpack2(acc[j][1], x1, y1);
            unpack2(acc[j][2], x2, y2);
            unpack2(acc[j][3], x3, y3);
            float4 o0 = make_float4(fmaxf(x0, 0.f), fmaxf(x1, 0.f),
                                    fmaxf(x2, 0.f), fmaxf(x3, 0.f));
            float4 o1 = make_float4(fmaxf(y0, 0.f), fmaxf(y1, 0.f),
                                    fmaxf(y2, 0.f), fmaxf(y3, 0.f));
            *(float4*)(out + (size_t)n * FDIM + colg * 4) = o0;
            *(float4*)(out + (size_t)(NNODES + n) * FDIM + colg * 4) = o1;
        }
    }
}

// ---------------------------------------------------------------------------
extern "C" void kernel_launch(void* const* d_in, const int* in_sizes, int n_in,
                              void* d_out, int out_size) {
    const float* nodes = (const float*)d_in[0];
    const int4* edges2 = (const int4*)d_in[1];   // int32 [E,2]
    const float* weight = (const float*)d_in[2];
    const float* bias = (const float*)d_in[3];
    float* out = (float*)d_out;

    int E = in_sizes[1] / 2;
    if (E > EDGES_MAX) E = EDGES_MAX;
    int Epairs = E / 2;

    k_hist<<<(Epairs + 255) / 256, 256>>>(edges2, Epairs);
    k_scan_local<<<SCAN_BLOCKS, 256>>>();
    k_scan_add<<<SCAN_BLOCKS, 256>>>();
    k_fill<<<(Epairs + 255) / 256, 256>>>(edges2, Epairs);
    k_fused<<<NBLOCKS, 256>>>(nodes, weight, bias, out);
}